// round 15
// baseline (speedup 1.0000x reference)
#include <cuda_runtime.h>
#include <math.h>

#define B_  4
#define H_  8
#define D_  512
#define HD_ 64
#define NQ_ 512
#define NK_ 4096

// exp(s/8) == exp2(s * 0.125 * log2(e))
#define EXPC 0.18033688011112042f

// ---------------- scratch (no-alloc rule) ----------------
__device__ float g_Q[(size_t)B_ * H_ * NQ_ * HD_];    // [bh][s][hd] tf32 bits
__device__ float g_K[(size_t)B_ * H_ * NK_ * HD_];    // k8-pair packed (attn)
__device__ float g_V[(size_t)B_ * H_ * NK_ * HD_];    // c-pair packed (attn)
__device__ float g_ctx[(size_t)B_ * NQ_ * D_];
// prepacked tf32 operands for proj_qkv
__device__ float g_Xq[(size_t)B_ * NQ_ * D_];
__device__ float g_Xk[(size_t)B_ * NK_ * D_];
__device__ float g_Xv[(size_t)B_ * NK_ * D_];
__device__ float g_Wq[(size_t)D_ * D_];
__device__ float g_Wk[(size_t)D_ * D_];
__device__ float g_Wv[(size_t)D_ * D_];

// ---------------- helpers ----------------
__device__ __forceinline__ unsigned f2tf32(float x) {
    unsigned r;
    asm("cvt.rna.tf32.f32 %0, %1;" : "=r"(r) : "f"(x));
    return r;
}

__device__ __forceinline__ void mma_tf32(float* d, const unsigned* a,
                                         const unsigned* b) {
    asm volatile(
        "mma.sync.aligned.m16n8k8.row.col.f32.tf32.tf32.f32 "
        "{%0,%1,%2,%3}, {%4,%5,%6,%7}, {%8,%9}, {%0,%1,%2,%3};"
        : "+f"(d[0]), "+f"(d[1]), "+f"(d[2]), "+f"(d[3])
        : "r"(a[0]), "r"(a[1]), "r"(a[2]), "r"(a[3]),
          "r"(b[0]), "r"(b[1]));
}

__device__ __forceinline__ void mma_tf32_u(float* d, const unsigned* a,
                                           unsigned b0, unsigned b1) {
    asm volatile(
        "mma.sync.aligned.m16n8k8.row.col.f32.tf32.tf32.f32 "
        "{%0,%1,%2,%3}, {%4,%5,%6,%7}, {%8,%9}, {%0,%1,%2,%3};"
        : "+f"(d[0]), "+f"(d[1]), "+f"(d[2]), "+f"(d[3])
        : "r"(a[0]), "r"(a[1]), "r"(a[2]), "r"(a[3]),
          "r"(b0), "r"(b1));
}

__device__ __forceinline__ void mma_tf32_f4(float* d, const float4& ra,
                                            const float4& rb, float b0, float b1) {
    asm volatile(
        "mma.sync.aligned.m16n8k8.row.col.f32.tf32.tf32.f32 "
        "{%0,%1,%2,%3}, {%4,%5,%6,%7}, {%8,%9}, {%0,%1,%2,%3};"
        : "+f"(d[0]), "+f"(d[1]), "+f"(d[2]), "+f"(d[3])
        : "r"(__float_as_uint(ra.x)), "r"(__float_as_uint(rb.x)),
          "r"(__float_as_uint(ra.y)), "r"(__float_as_uint(rb.y)),
          "r"(__float_as_uint(b0)), "r"(__float_as_uint(b1)));
}

__device__ __forceinline__ void cpa16(unsigned dst, const void* src) {
    asm volatile("cp.async.cg.shared.global [%0], [%1], 16;\n"
                 :: "r"(dst), "l"(src));
}
__device__ __forceinline__ void cpa_commit() {
    asm volatile("cp.async.commit_group;\n" ::: "memory");
}
template <int N>
__device__ __forceinline__ void cpa_wait() {
    asm volatile("cp.async.wait_group %0;\n" :: "n"(N) : "memory");
}

// ---------------------------------------------------------------------------
// Prepack: tf32-convert + fragment-pair pack X and W operands. (unchanged)
// ---------------------------------------------------------------------------
__global__ __launch_bounds__(256) void prepack(
    const float* __restrict__ q, const float* __restrict__ k,
    const float* __restrict__ v, const float* __restrict__ Wq,
    const float* __restrict__ Wk, const float* __restrict__ Wv,
    float* __restrict__ Xq, float* __restrict__ Xk, float* __restrict__ Xv,
    float* __restrict__ Pq, float* __restrict__ Pk, float* __restrict__ Pv)
{
    int ci  = blockIdx.x * 256 + threadIdx.x;
    int row = ci >> 7;
    int cr  = ci & 127;

    const float* src; float* dst; int lrow;
    if (row < 2048)       { src = q;  dst = Xq; lrow = row; }
    else if (row < 18432) { src = k;  dst = Xk; lrow = row - 2048; }
    else if (row < 34816) { src = v;  dst = Xv; lrow = row - 18432; }
    else if (row < 35328) { src = Wq; dst = Pq; lrow = row - 34816; }
    else if (row < 35840) { src = Wk; dst = Pk; lrow = row - 35328; }
    else                  { src = Wv; dst = Pv; lrow = row - 35840; }

    int ki = cr >> 3, u = cr & 7;
    int t = u & 3;
    int p = (u >> 2) ^ (lrow & 1);
    const float* s = src + (size_t)lrow * D_ + ki * 32 + p * 16 + t;
    float4 o;
    o.x = __uint_as_float(f2tf32(s[0]));
    o.y = __uint_as_float(f2tf32(s[4]));
    o.z = __uint_as_float(f2tf32(s[8]));
    o.w = __uint_as_float(f2tf32(s[12]));
    *reinterpret_cast<float4*>(dst + (size_t)lrow * D_ + ki * 32 + u * 4) = o;
}

// ---------------------------------------------------------------------------
// Fused Q/K/V projection from PREPACKED operands (unchanged from R13).
// ---------------------------------------------------------------------------
#define PKSTG 4096   // 128 rows * 32 floats per stage per matrix

__global__ __launch_bounds__(256, 2) void proj_qkv(
    const float* __restrict__ Xq, const float* __restrict__ Pq, const float* __restrict__ bq,
    const float* __restrict__ Xk, const float* __restrict__ Pk, const float* __restrict__ bk,
    const float* __restrict__ Xv, const float* __restrict__ Pv, const float* __restrict__ bv,
    float* __restrict__ Yq, float* __restrict__ Yk, float* __restrict__ Yv)
{
    extern __shared__ float psm[];
    float* Xs = psm;
    float* Ws = psm + 2 * PKSTG;

    const float *X, *W, *bias;
    float* Y;
    int mode, bxt, N_seq;
    if (blockIdx.x < 16)       { X = Xq; W = Pq; bias = bq; Y = Yq; mode = 0; bxt = blockIdx.x;      N_seq = NQ_; }
    else if (blockIdx.x < 144) { X = Xk; W = Pk; bias = bk; Y = Yk; mode = 1; bxt = blockIdx.x - 16; N_seq = NK_; }
    else                       { X = Xv; W = Pv; bias = bv; Y = Yv; mode = 2; bxt = blockIdx.x - 144; N_seq = NK_; }

    const int tid  = threadIdx.x;
    const int lane = tid & 31;
    const int w    = tid >> 5;
    const int wm   = w >> 2;
    const int wn   = w & 3;
    const int g    = lane >> 2;
    const int t    = lane & 3;
    const int bm   = bxt * 128;
    const int bn   = blockIdx.y * 128;
    const int swz  = (g & 1) << 2;

    unsigned xs_u = (unsigned)__cvta_generic_to_shared(Xs);
    unsigned ws_u = (unsigned)__cvta_generic_to_shared(Ws);

    float acc[4][4][4];
#pragma unroll
    for (int mi = 0; mi < 4; mi++)
#pragma unroll
        for (int nj = 0; nj < 4; nj++)
#pragma unroll
            for (int rr = 0; rr < 4; rr++) acc[mi][nj][rr] = 0.0f;

#pragma unroll
    for (int it = 0; it < 4; it++) {
        int i = it * 256 + tid;
        int r = i >> 3, c = (i & 7) * 4;
        cpa16(xs_u + (r * 32 + c) * 4, X + (size_t)(bm + r) * D_ + c);
        cpa16(ws_u + (r * 32 + c) * 4, W + (size_t)(bn + r) * D_ + c);
    }
    cpa_commit();

    for (int ki = 0; ki < 16; ki++) {
        cpa_wait<0>();
        __syncthreads();
        if (ki < 15) {
            int st = ((ki + 1) & 1) * PKSTG;
            int k0 = (ki + 1) * 32;
#pragma unroll
            for (int it = 0; it < 4; it++) {
                int i = it * 256 + tid;
                int r = i >> 3, c = (i & 7) * 4;
                cpa16(xs_u + (st + r * 32 + c) * 4,
                      X + (size_t)(bm + r) * D_ + k0 + c);
                cpa16(ws_u + (st + r * 32 + c) * 4,
                      W + (size_t)(bn + r) * D_ + k0 + c);
            }
            cpa_commit();
        }
        const float4* Xc = reinterpret_cast<const float4*>(Xs + (ki & 1) * PKSTG);
        const float4* Wc = reinterpret_cast<const float4*>(Ws + (ki & 1) * PKSTG);

#pragma unroll
        for (int p = 0; p < 2; p++) {
            int up = ((p << 2) + t) ^ swz;
            float4 ua[4], ub[4], vb[4];
#pragma unroll
            for (int mi = 0; mi < 4; mi++) {
                int r = wm * 64 + mi * 16 + g;
                ua[mi] = Xc[r * 8 + up];
                ub[mi] = Xc[(r + 8) * 8 + up];
            }
#pragma unroll
            for (int nj = 0; nj < 4; nj++) {
                int n = wn * 32 + nj * 8 + g;
                vb[nj] = Wc[n * 8 + up];
            }
#pragma unroll
            for (int mi = 0; mi < 4; mi++)
#pragma unroll
                for (int nj = 0; nj < 4; nj++) {
                    mma_tf32_f4(acc[mi][nj], ua[mi], ub[mi], vb[nj].x, vb[nj].y);
                    float4 ta = make_float4(ua[mi].z, ua[mi].w, 0.f, 0.f);
                    float4 tb = make_float4(ub[mi].z, ub[mi].w, 0.f, 0.f);
                    mma_tf32_f4(acc[mi][nj], ta, tb, vb[nj].z, vb[nj].w);
                }
        }
    }

#pragma unroll
    for (int mi = 0; mi < 4; mi++) {
#pragma unroll
        for (int nj = 0; nj < 4; nj++) {
            int n = bn + wn * 32 + nj * 8 + t * 2;
            float b0 = bias[n], b1 = bias[n + 1];
#pragma unroll
            for (int rr = 0; rr < 2; rr++) {
                int m = bm + wm * 64 + mi * 16 + g + rr * 8;
                float v0 = __uint_as_float(f2tf32(acc[mi][nj][rr * 2] + b0));
                float v1 = __uint_as_float(f2tf32(acc[mi][nj][rr * 2 + 1] + b1));
                int s  = m & (N_seq - 1);
                int bb = m / N_seq;
                int h  = n >> 6;
                int hd = n & 63;
                int bh = bb * H_ + h;
                if (mode == 0) {
                    *reinterpret_cast<float2*>(
                        &Y[(((size_t)bh * NQ_ + s) << 6) + hd]) = make_float2(v0, v1);
                } else if (mode == 1) {
                    size_t base2 = (((size_t)bh * NK_ + s)) * 32;
                    int o  = ((hd >> 4) << 3) + (hd & 3) * 2 + ((hd >> 3) & 1);
                    int hf = (hd >> 2) & 1;
                    Y[(base2 + o) * 2 + hf]     = v0;
                    Y[(base2 + o + 2) * 2 + hf] = v1;
                } else {
                    int sl = s & 63;
                    int o  = ((sl >> 4) << 3) + (sl & 3) * 2 + ((sl >> 3) & 1);
                    int hf = (sl >> 2) & 1;
                    size_t base2 = (((size_t)bh * (NK_ / 64) + (s >> 6)) * 64 + hd) * 32;
                    Y[(base2 + o) * 2 + hf]      = v0;
                    Y[(base2 + 32 + o) * 2 + hf] = v1;
                }
            }
        }
    }
}

// ---------------------------------------------------------------------------
// Output projection (unchanged).
// ---------------------------------------------------------------------------
#define PSTG 4608

__global__ __launch_bounds__(256, 2) void proj_out(
    const float* __restrict__ X, const float* __restrict__ W,
    const float* __restrict__ bias, float* __restrict__ Y)
{
    extern __shared__ float psm[];
    float* Xs = psm;
    float* Ws = psm + 2 * PSTG;

    const int tid  = threadIdx.x;
    const int lane = tid & 31;
    const int w    = tid >> 5;
    const int wm   = w >> 2;
    const int wn   = w & 3;
    const int g    = lane >> 2;
    const int t    = lane & 3;
    const int bm   = blockIdx.x * 128;
    const int bn   = blockIdx.y * 128;

    unsigned xs_u = (unsigned)__cvta_generic_to_shared(Xs);
    unsigned ws_u = (unsigned)__cvta_generic_to_shared(Ws);

    float acc[4][4][4];
#pragma unroll
    for (int mi = 0; mi < 4; mi++)
#pragma unroll
        for (int nj = 0; nj < 4; nj++)
#pragma unroll
            for (int rr = 0; rr < 4; rr++) acc[mi][nj][rr] = 0.0f;

#pragma unroll
    for (int it = 0; it < 4; it++) {
        int i = it * 256 + tid;
        int r = i >> 3, c = (i & 7) * 4;
        cpa16(xs_u + (r * 36 + c) * 4, X + (size_t)(bm + r) * D_ + c);
        cpa16(ws_u + (r * 36 + c) * 4, W + (size_t)(bn + r) * D_ + c);
    }
    cpa_commit();

    for (int ki = 0; ki < 16; ki++) {
        cpa_wait<0>();
        __syncthreads();
        if (ki < 15) {
            int st = ((ki + 1) & 1) * PSTG;
            int k0 = (ki + 1) * 32;
#pragma unroll
            for (int it = 0; it < 4; it++) {
                int i = it * 256 + tid;
                int r = i >> 3, c = (i & 7) * 4;
                cpa16(xs_u + (st + r * 36 + c) * 4,
                      X + (size_t)(bm + r) * D_ + k0 + c);
                cpa16(ws_u + (st + r * 36 + c) * 4,
                      W + (size_t)(bn + r) * D_ + k0 + c);
            }
            cpa_commit();
        }
        const float* Xc = Xs + (ki & 1) * PSTG;
        const float* Wc = Ws + (ki & 1) * PSTG;

#pragma unroll
        for (int k8 = 0; k8 < 4; k8++) {
            unsigned a[4][4], b[4][2];
            int kk = k8 * 8 + t;
#pragma unroll
            for (int mi = 0; mi < 4; mi++) {
                int r = wm * 64 + mi * 16 + g;
                a[mi][0] = f2tf32(Xc[r * 36 + kk]);
                a[mi][1] = f2tf32(Xc[(r + 8) * 36 + kk]);
                a[mi][2] = f2tf32(Xc[r * 36 + kk + 4]);
                a[mi][3] = f2tf32(Xc[(r + 8) * 36 + kk + 4]);
            }
#pragma unroll
            for (int nj = 0; nj < 4; nj++) {
                int n = wn * 32 + nj * 8 + g;
                b[nj][0] = f2tf32(Wc[n * 36 + kk]);
                b[nj][1] = f2tf32(Wc[n * 36 + kk + 4]);
            }
#pragma unroll
            for (int mi = 0; mi < 4; mi++)
#pragma unroll
                for (int nj = 0; nj < 4; nj++)
                    mma_tf32(acc[mi][nj], a[mi], b[nj]);
        }
    }

#pragma unroll
    for (int mi = 0; mi < 4; mi++) {
#pragma unroll
        for (int nj = 0; nj < 4; nj++) {
            int n = bn + wn * 32 + nj * 8 + t * 2;
            float b0 = bias[n], b1 = bias[n + 1];
#pragma unroll
            for (int rr = 0; rr < 2; rr++) {
                int m = bm + wm * 64 + mi * 16 + g + rr * 8;
                *reinterpret_cast<float2*>(&Y[(size_t)m * D_ + n]) =
                    make_float2(acc[mi][nj][rr * 2] + b0,
                                acc[mi][nj][rr * 2 + 1] + b1);
            }
        }
    }
}

// ---------------------------------------------------------------------------
// Attention v3: CTA = 32 q-rows, 4 warps = (wq: q-half) x (wc: tile-col-half).
// Grid 512. Per warp: 16 q rows x 32 tile cols. Row-sum and ctx partials
// combined across wc via smem. K/V layouts + LDS.128 frags unchanged.
// ---------------------------------------------------------------------------
#define KBUFB 16384            // 64 rows * 32 f2 * 8B
#define VBUFB 16384
#define OFRED (2 * KBUFB + 2 * VBUFB)        // 65536
#define ATT_SMEM_BYTES (OFRED + 256)         // + red[64]

__global__ __launch_bounds__(128, 3) void attn_tc(
    const float* __restrict__ gQ, const float* __restrict__ gK,
    const float* __restrict__ gV, float* __restrict__ A_out,
    float* __restrict__ gctx)
{
    extern __shared__ char smc[];
    char* Kb = smc;                  // [2][KBUFB]
    char* Vb = smc + 2 * KBUFB;      // [2][VBUFB]
    float* red = (float*)(smc + OFRED);   // [2][32]

    const int tid  = threadIdx.x;
    const int lane = tid & 31;
    const int w    = tid >> 5;
    const int g    = lane >> 2;
    const int t    = lane & 3;
    const int wq   = w & 1;          // q-half (16 rows)
    const int wc   = w >> 1;         // tile-col half (32 cols)
    const int bh   = blockIdx.x >> 4;
    const int qt   = blockIdx.x & 15;
    const int sw   = (g & 1) << 2;
    const int row0 = wq * 16 + g;    // CTA-local q row

    const float*  Qg  = gQ + ((size_t)bh * NQ_ + qt * 32 + wq * 16) * HD_;
    const float2* Kg2 = (const float2*)gK + (size_t)bh * NK_ * 32;
    const float2* Vg2 = (const float2*)gV + (size_t)bh * NK_ * 32;
    float* Ab = A_out + ((size_t)bh * NQ_ + qt * 32) * NK_;

    unsigned kb_u = (unsigned)__cvta_generic_to_shared(Kb);
    unsigned vb_u = (unsigned)__cvta_generic_to_shared(Vb);

    // Q fragments (warp's 16 rows), reused for all tiles
    unsigned qa[8][4];
#pragma unroll
    for (int k8 = 0; k8 < 8; k8++) {
        int kk = k8 * 8 + t;
        qa[k8][0] = __float_as_uint(Qg[(size_t)g * HD_ + kk]);
        qa[k8][1] = __float_as_uint(Qg[(size_t)(g + 8) * HD_ + kk]);
        qa[k8][2] = __float_as_uint(Qg[(size_t)g * HD_ + kk + 4]);
        qa[k8][3] = __float_as_uint(Qg[(size_t)(g + 8) * HD_ + kk + 4]);
    }

    const int cr = tid >> 4;
    const int cc = tid & 15;

    // ================= PHASE 1: partial row sums =================
#pragma unroll
    for (int it = 0; it < 8; it++) {
        int r = it * 8 + cr;
        cpa16(kb_u + (r * 16 + (cc ^ ((r & 1) << 2))) * 16,
              Kg2 + (size_t)r * 32 + cc * 2);
    }
    cpa_commit();

    float psum0 = 0.0f, psum1 = 0.0f;

    for (int kt = 0; kt < 64; kt++) {
        cpa_wait<0>();
        __syncthreads();
        if (kt < 63) {
            const float2* Kn = Kg2 + (size_t)(kt + 1) * 64 * 32;
            unsigned kdst = kb_u + ((kt + 1) & 1) * KBUFB;
#pragma unroll
            for (int it = 0; it < 8; it++) {
                int r = it * 8 + cr;
                cpa16(kdst + (r * 16 + (cc ^ ((r & 1) << 2))) * 16,
                      Kn + (size_t)r * 32 + cc * 2);
            }
            cpa_commit();
        }
        const char* Ksm = Kb + (kt & 1) * KBUFB;

        float s[4][4];
#pragma unroll
        for (int nj = 0; nj < 4; nj++)
#pragma unroll
            for (int rr = 0; rr < 4; rr++) s[nj][rr] = 0.0f;

#pragma unroll
        for (int p = 0; p < 4; p++) {
#pragma unroll
            for (int nj = 0; nj < 4; nj++) {
                int unit = (wc * 32 + nj * 8 + g) * 16 + ((p * 4 + t) ^ sw);
                float4 u = *reinterpret_cast<const float4*>(Ksm + unit * 16);
                mma_tf32_u(s[nj], qa[2 * p],
                           __float_as_uint(u.x), __float_as_uint(u.y));
                mma_tf32_u(s[nj], qa[2 * p + 1],
                           __float_as_uint(u.z), __float_as_uint(u.w));
            }
        }

#pragma unroll
        for (int nj = 0; nj < 4; nj++) {
            psum0 += exp2f(s[nj][0] * EXPC) + exp2f(s[nj][1] * EXPC);
            psum1 += exp2f(s[nj][2] * EXPC) + exp2f(s[nj][3] * EXPC);
        }
    }

    psum0 += __shfl_xor_sync(0xffffffffu, psum0, 1);
    psum0 += __shfl_xor_sync(0xffffffffu, psum0, 2);
    psum1 += __shfl_xor_sync(0xffffffffu, psum1, 1);
    psum1 += __shfl_xor_sync(0xffffffffu, psum1, 2);
    if (t == 0) {
        red[wc * 32 + row0]     = psum0;
        red[wc * 32 + row0 + 8] = psum1;
    }
    __syncthreads();
    const float li0 = 1.0f / (red[row0] + red[32 + row0]);
    const float li1 = 1.0f / (red[row0 + 8] + red[32 + row0 + 8]);

    // ================= PHASE 2: A + partial ctx =================
#pragma unroll
    for (int it = 0; it < 8; it++) {
        int r = it * 8 + cr;
        unsigned doff = (r * 16 + (cc ^ ((r & 1) << 2))) * 16;
        cpa16(kb_u + doff, Kg2 + (size_t)r * 32 + cc * 2);
        cpa16(vb_u + doff, Vg2 + (size_t)r * 32 + cc * 2);
    }
    cpa_commit();

    float ctx[8][4];
#pragma unroll
    for (int nj = 0; nj < 8; nj++)
#pragma unroll
        for (int rr = 0; rr < 4; rr++) ctx[nj][rr] = 0.0f;

    const int srcA = (lane & ~3) | (t >> 1);
    const int srcB = srcA + 2;
    const bool sel = (t & 1);

    for (int kt = 0; kt < 64; kt++) {
        cpa_wait<0>();
        __syncthreads();
        if (kt < 63) {
            const float2* Kn = Kg2 + (size_t)(kt + 1) * 64 * 32;
            const float2* Vn = Vg2 + (size_t)(kt + 1) * 64 * 32;
            unsigned kdst = kb_u + ((kt + 1) & 1) * KBUFB;
            unsigned vdst = vb_u + ((kt + 1) & 1) * VBUFB;
#pragma unroll
            for (int it = 0; it < 8; it++) {
                int r = it * 8 + cr;
                unsigned doff = (r * 16 + (cc ^ ((r & 1) << 2))) * 16;
                cpa16(kdst + doff, Kn + (size_t)r * 32 + cc * 2);
                cpa16(vdst + doff, Vn + (size_t)r * 32 + cc * 2);
            }
            cpa_commit();
        }
        const char* Ksm = Kb + (kt & 1) * KBUFB;
        const char* Vsm = Vb + (kt & 1) * VBUFB;

        // ---- S = Q K^T (this warp's 32 tile cols) ----
        float s[4][4];
#pragma unroll
        for (int nj = 0; nj < 4; nj++)
#pragma unroll
            for (int rr = 0; rr < 4; rr++) s[nj][rr] = 0.0f;

#pragma unroll
        for (int p = 0; p < 4; p++) {
#pragma unroll
            for (int nj = 0; nj < 4; nj++) {
                int unit = (wc * 32 + nj * 8 + g) * 16 + ((p * 4 + t) ^ sw);
                float4 u = *reinterpret_cast<const float4*>(Ksm + unit * 16);
                mma_tf32_u(s[nj], qa[2 * p],
                           __float_as_uint(u.x), __float_as_uint(u.y));
                mma_tf32_u(s[nj], qa[2 * p + 1],
                           __float_as_uint(u.z), __float_as_uint(u.w));
            }
        }

        // ---- normalized P: write A once, keep tf32 bits ----
        unsigned u0[4], u1[4], u2[4], u3[4];
#pragma unroll
        for (int nj = 0; nj < 4; nj++) {
            float p0 = exp2f(s[nj][0] * EXPC) * li0;
            float p1 = exp2f(s[nj][1] * EXPC) * li0;
            float p2 = exp2f(s[nj][2] * EXPC) * li1;
            float p3 = exp2f(s[nj][3] * EXPC) * li1;
            int col = kt * 64 + wc * 32 + nj * 8 + t * 2;
            *reinterpret_cast<float2*>(
                &Ab[(size_t)row0 * NK_ + col]) = make_float2(p0, p1);
            *reinterpret_cast<float2*>(
                &Ab[(size_t)(row0 + 8) * NK_ + col]) = make_float2(p2, p3);
            u0[nj] = f2tf32(p0);
            u1[nj] = f2tf32(p1);
            u2[nj] = f2tf32(p2);
            u3[nj] = f2tf32(p3);
        }

        // ---- ctx += P V over this warp's 32 k-rows ----
#pragma unroll
        for (int p2i = 0; p2i < 2; p2i++) {
            unsigned paE[4], paO[4];
#pragma unroll
            for (int e = 0; e < 2; e++) {
                int c = 2 * p2i + e;
                unsigned x0 = __shfl_sync(0xffffffffu, u0[c], srcA);
                unsigned x1 = __shfl_sync(0xffffffffu, u1[c], srcA);
                unsigned y0 = __shfl_sync(0xffffffffu, u0[c], srcB);
                unsigned y1 = __shfl_sync(0xffffffffu, u1[c], srcB);
                unsigned z0 = __shfl_sync(0xffffffffu, u2[c], srcA);
                unsigned z1 = __shfl_sync(0xffffffffu, u3[c], srcA);
                unsigned w0 = __shfl_sync(0xffffffffu, u2[c], srcB);
                unsigned w1 = __shfl_sync(0xffffffffu, u3[c], srcB);
                unsigned* pa = e ? paO : paE;
                pa[0] = sel ? x1 : x0;
                pa[1] = sel ? z1 : z0;
                pa[2] = sel ? y1 : y0;
                pa[3] = sel ? w1 : w0;
            }
            int pg = 2 * wc + p2i;       // global k8-pair within the 64-row tile
#pragma unroll
            for (int nj2 = 0; nj2 < 8; nj2++) {
                int unit = (nj2 * 8 + g) * 16 + ((pg * 4 + t) ^ sw);
                float4 u = *reinterpret_cast<const float4*>(Vsm + unit * 16);
                mma_tf32_u(ctx[nj2], paE,
                           __float_as_uint(u.x), __float_as_uint(u.y));
                mma_tf32_u(ctx[nj2], paO,
                           __float_as_uint(u.z), __float_as_uint(u.w));
            }
        }
    }

    // ---- combine ctx across wc halves via smem, then write ----
    __syncthreads();
    float* cbuf = (float*)smc;           // 32 rows x stride 66
    if (wc == 1) {
#pragma unroll
        for (int nj2 = 0; nj2 < 8; nj2++) {
            int c0 = nj2 * 8 + t * 2;
            *reinterpret_cast<float2*>(&cbuf[row0 * 66 + c0]) =
                make_float2(ctx[nj2][0], ctx[nj2][1]);
            *reinterpret_cast<float2*>(&cbuf[(row0 + 8) * 66 + c0]) =
                make_float2(ctx[nj2][2], ctx[nj2][3]);
        }
    }
    __syncthreads();
    if (wc == 0) {
        const int b0 = bh >> 3;
        const int h  = bh & 7;
#pragma unroll
        for (int nj2 = 0; nj2 < 8; nj2++) {
            int hd = nj2 * 8 + t * 2;
#pragma unroll
            for (int rr = 0; rr < 2; rr++) {
                int r = row0 + rr * 8;
                float2 o = *reinterpret_cast<const float2*>(&cbuf[r * 66 + hd]);
                int q = qt * 32 + r;
                float2 v = make_float2(ctx[nj2][rr * 2] + o.x,
                                       ctx[nj2][rr * 2 + 1] + o.y);
                *reinterpret_cast<float2*>(
                    &gctx[((size_t)b0 * NQ_ + q) * D_ + h * 64 + hd]) = v;
            }
        }
    }
}

// ---------------------------------------------------------------------------
extern "C" void kernel_launch(void* const* d_in, const int* in_sizes, int n_in,
                              void* d_out, int out_size)
{
    const float* q  = (const float*)d_in[0];
    const float* k  = (const float*)d_in[1];
    const float* v  = (const float*)d_in[2];
    const float* Wq = (const float*)d_in[3];
    const float* bq = (const float*)d_in[4];
    const float* Wk = (const float*)d_in[5];
    const float* bk = (const float*)d_in[6];
    const float* Wv = (const float*)d_in[7];
    const float* bv = (const float*)d_in[8];
    const float* Wo = (const float*)d_in[9];
    const float* bo = (const float*)d_in[10];

    float* out = (float*)d_out;                         // [B, NQ, D]
    float* A   = out + (size_t)B_ * NQ_ * D_;           // [B, H, NQ, NK]

    float *gQ, *gK, *gV, *gctx, *gXq, *gXk, *gXv, *gWq, *gWk, *gWv;
    cudaGetSymbolAddress((void**)&gQ,  g_Q);
    cudaGetSymbolAddress((void**)&gK,  g_K);
    cudaGetSymbolAddress((void**)&gV,  g_V);
    cudaGetSymbolAddress((void**)&gctx, g_ctx);
    cudaGetSymbolAddress((void**)&gXq, g_Xq);
    cudaGetSymbolAddress((void**)&gXk, g_Xk);
    cudaGetSymbolAddress((void**)&gXv, g_Xv);
    cudaGetSymbolAddress((void**)&gWq, g_Wq);
    cudaGetSymbolAddress((void**)&gWk, g_Wk);
    cudaGetSymbolAddress((void**)&gWv, g_Wv);

    const int pk_smem = 4 * PKSTG * 4;    // 65536 B
    const int po_smem = 4 * PSTG * 4;     // 73728 B
    cudaFuncSetAttribute(proj_qkv,
        cudaFuncAttributeMaxDynamicSharedMemorySize, pk_smem);
    cudaFuncSetAttribute(proj_out,
        cudaFuncAttributeMaxDynamicSharedMemorySize, po_smem);
    cudaFuncSetAttribute(attn_tc,
        cudaFuncAttributeMaxDynamicSharedMemorySize, ATT_SMEM_BYTES);

    prepack<<<18176, 256>>>(q, k, v, Wq, Wk, Wv,
                            gXq, gXk, gXv, gWq, gWk, gWv);
    proj_qkv<<<dim3(272, 4), 256, pk_smem>>>(
        gXq, gWq, bq, gXk, gWk, bk, gXv, gWv, bv, gQ, gK, gV);
    attn_tc<<<512, 128, ATT_SMEM_BYTES>>>(gQ, gK, gV, A, gctx);
    proj_out<<<dim3(16, 4), 256, po_smem>>>(gctx, Wo, bo, out);
}

// round 17
// speedup vs baseline: 1.6498x; 1.6498x over previous
#include <cuda_runtime.h>
#include <math.h>

#define B_  4
#define H_  8
#define D_  512
#define HD_ 64
#define NQ_ 512
#define NK_ 4096

// exp(s/8) == exp2(s * 0.125 * log2(e))
#define EXPC 0.18033688011112042f

// ---------------- scratch (no-alloc rule) ----------------
__device__ float g_Q[(size_t)B_ * H_ * NQ_ * HD_];    // [bh][s][hd] tf32 bits
__device__ float g_K[(size_t)B_ * H_ * NK_ * HD_];    // k8-pair packed (attn)
__device__ float g_V[(size_t)B_ * H_ * NK_ * HD_];    // c-pair packed (attn)
__device__ float g_ctx[(size_t)B_ * NQ_ * D_];
// prepacked tf32 operands for proj_qkv
__device__ float g_Xq[(size_t)B_ * NQ_ * D_];
__device__ float g_Xk[(size_t)B_ * NK_ * D_];
__device__ float g_Xv[(size_t)B_ * NK_ * D_];
__device__ float g_Wq[(size_t)D_ * D_];
__device__ float g_Wk[(size_t)D_ * D_];
__device__ float g_Wv[(size_t)D_ * D_];

// ---------------- helpers ----------------
__device__ __forceinline__ unsigned f2tf32(float x) {
    unsigned r;
    asm("cvt.rna.tf32.f32 %0, %1;" : "=r"(r) : "f"(x));
    return r;
}

__device__ __forceinline__ void mma_tf32(float* d, const unsigned* a,
                                         const unsigned* b) {
    asm volatile(
        "mma.sync.aligned.m16n8k8.row.col.f32.tf32.tf32.f32 "
        "{%0,%1,%2,%3}, {%4,%5,%6,%7}, {%8,%9}, {%0,%1,%2,%3};"
        : "+f"(d[0]), "+f"(d[1]), "+f"(d[2]), "+f"(d[3])
        : "r"(a[0]), "r"(a[1]), "r"(a[2]), "r"(a[3]),
          "r"(b[0]), "r"(b[1]));
}

__device__ __forceinline__ void mma_tf32_u(float* d, const unsigned* a,
                                           unsigned b0, unsigned b1) {
    asm volatile(
        "mma.sync.aligned.m16n8k8.row.col.f32.tf32.tf32.f32 "
        "{%0,%1,%2,%3}, {%4,%5,%6,%7}, {%8,%9}, {%0,%1,%2,%3};"
        : "+f"(d[0]), "+f"(d[1]), "+f"(d[2]), "+f"(d[3])
        : "r"(a[0]), "r"(a[1]), "r"(a[2]), "r"(a[3]),
          "r"(b0), "r"(b1));
}

__device__ __forceinline__ void mma_tf32_f4(float* d, const float4& ra,
                                            const float4& rb, float b0, float b1) {
    asm volatile(
        "mma.sync.aligned.m16n8k8.row.col.f32.tf32.tf32.f32 "
        "{%0,%1,%2,%3}, {%4,%5,%6,%7}, {%8,%9}, {%0,%1,%2,%3};"
        : "+f"(d[0]), "+f"(d[1]), "+f"(d[2]), "+f"(d[3])
        : "r"(__float_as_uint(ra.x)), "r"(__float_as_uint(rb.x)),
          "r"(__float_as_uint(ra.y)), "r"(__float_as_uint(rb.y)),
          "r"(__float_as_uint(b0)), "r"(__float_as_uint(b1)));
}

__device__ __forceinline__ void cpa16(unsigned dst, const void* src) {
    asm volatile("cp.async.cg.shared.global [%0], [%1], 16;\n"
                 :: "r"(dst), "l"(src));
}
__device__ __forceinline__ void cpa_commit() {
    asm volatile("cp.async.commit_group;\n" ::: "memory");
}
template <int N>
__device__ __forceinline__ void cpa_wait() {
    asm volatile("cp.async.wait_group %0;\n" :: "n"(N) : "memory");
}

// ---------------------------------------------------------------------------
// Prepack: tf32-convert + fragment-pair pack X and W operands. (unchanged)
// ---------------------------------------------------------------------------
__global__ __launch_bounds__(256) void prepack(
    const float* __restrict__ q, const float* __restrict__ k,
    const float* __restrict__ v, const float* __restrict__ Wq,
    const float* __restrict__ Wk, const float* __restrict__ Wv,
    float* __restrict__ Xq, float* __restrict__ Xk, float* __restrict__ Xv,
    float* __restrict__ Pq, float* __restrict__ Pk, float* __restrict__ Pv)
{
    int ci  = blockIdx.x * 256 + threadIdx.x;
    int row = ci >> 7;
    int cr  = ci & 127;

    const float* src; float* dst; int lrow;
    if (row < 2048)       { src = q;  dst = Xq; lrow = row; }
    else if (row < 18432) { src = k;  dst = Xk; lrow = row - 2048; }
    else if (row < 34816) { src = v;  dst = Xv; lrow = row - 18432; }
    else if (row < 35328) { src = Wq; dst = Pq; lrow = row - 34816; }
    else if (row < 35840) { src = Wk; dst = Pk; lrow = row - 35328; }
    else                  { src = Wv; dst = Pv; lrow = row - 35840; }

    int ki = cr >> 3, u = cr & 7;
    int t = u & 3;
    int p = (u >> 2) ^ (lrow & 1);
    const float* s = src + (size_t)lrow * D_ + ki * 32 + p * 16 + t;
    float4 o;
    o.x = __uint_as_float(f2tf32(s[0]));
    o.y = __uint_as_float(f2tf32(s[4]));
    o.z = __uint_as_float(f2tf32(s[8]));
    o.w = __uint_as_float(f2tf32(s[12]));
    *reinterpret_cast<float4*>(dst + (size_t)lrow * D_ + ki * 32 + u * 4) = o;
}

// ---------------------------------------------------------------------------
// Fused Q/K/V projection from PREPACKED operands (unchanged from R13).
// ---------------------------------------------------------------------------
#define PKSTG 4096   // 128 rows * 32 floats per stage per matrix

__global__ __launch_bounds__(256, 2) void proj_qkv(
    const float* __restrict__ Xq, const float* __restrict__ Pq, const float* __restrict__ bq,
    const float* __restrict__ Xk, const float* __restrict__ Pk, const float* __restrict__ bk,
    const float* __restrict__ Xv, const float* __restrict__ Pv, const float* __restrict__ bv,
    float* __restrict__ Yq, float* __restrict__ Yk, float* __restrict__ Yv)
{
    extern __shared__ float psm[];
    float* Xs = psm;
    float* Ws = psm + 2 * PKSTG;

    const float *X, *W, *bias;
    float* Y;
    int mode, bxt, N_seq;
    if (blockIdx.x < 16)       { X = Xq; W = Pq; bias = bq; Y = Yq; mode = 0; bxt = blockIdx.x;      N_seq = NQ_; }
    else if (blockIdx.x < 144) { X = Xk; W = Pk; bias = bk; Y = Yk; mode = 1; bxt = blockIdx.x - 16; N_seq = NK_; }
    else                       { X = Xv; W = Pv; bias = bv; Y = Yv; mode = 2; bxt = blockIdx.x - 144; N_seq = NK_; }

    const int tid  = threadIdx.x;
    const int lane = tid & 31;
    const int w    = tid >> 5;
    const int wm   = w >> 2;
    const int wn   = w & 3;
    const int g    = lane >> 2;
    const int t    = lane & 3;
    const int bm   = bxt * 128;
    const int bn   = blockIdx.y * 128;
    const int swz  = (g & 1) << 2;

    unsigned xs_u = (unsigned)__cvta_generic_to_shared(Xs);
    unsigned ws_u = (unsigned)__cvta_generic_to_shared(Ws);

    float acc[4][4][4];
#pragma unroll
    for (int mi = 0; mi < 4; mi++)
#pragma unroll
        for (int nj = 0; nj < 4; nj++)
#pragma unroll
            for (int rr = 0; rr < 4; rr++) acc[mi][nj][rr] = 0.0f;

#pragma unroll
    for (int it = 0; it < 4; it++) {
        int i = it * 256 + tid;
        int r = i >> 3, c = (i & 7) * 4;
        cpa16(xs_u + (r * 32 + c) * 4, X + (size_t)(bm + r) * D_ + c);
        cpa16(ws_u + (r * 32 + c) * 4, W + (size_t)(bn + r) * D_ + c);
    }
    cpa_commit();

    for (int ki = 0; ki < 16; ki++) {
        cpa_wait<0>();
        __syncthreads();
        if (ki < 15) {
            int st = ((ki + 1) & 1) * PKSTG;
            int k0 = (ki + 1) * 32;
#pragma unroll
            for (int it = 0; it < 4; it++) {
                int i = it * 256 + tid;
                int r = i >> 3, c = (i & 7) * 4;
                cpa16(xs_u + (st + r * 32 + c) * 4,
                      X + (size_t)(bm + r) * D_ + k0 + c);
                cpa16(ws_u + (st + r * 32 + c) * 4,
                      W + (size_t)(bn + r) * D_ + k0 + c);
            }
            cpa_commit();
        }
        const float4* Xc = reinterpret_cast<const float4*>(Xs + (ki & 1) * PKSTG);
        const float4* Wc = reinterpret_cast<const float4*>(Ws + (ki & 1) * PKSTG);

#pragma unroll
        for (int p = 0; p < 2; p++) {
            int up = ((p << 2) + t) ^ swz;
            float4 ua[4], ub[4], vb[4];
#pragma unroll
            for (int mi = 0; mi < 4; mi++) {
                int r = wm * 64 + mi * 16 + g;
                ua[mi] = Xc[r * 8 + up];
                ub[mi] = Xc[(r + 8) * 8 + up];
            }
#pragma unroll
            for (int nj = 0; nj < 4; nj++) {
                int n = wn * 32 + nj * 8 + g;
                vb[nj] = Wc[n * 8 + up];
            }
#pragma unroll
            for (int mi = 0; mi < 4; mi++)
#pragma unroll
                for (int nj = 0; nj < 4; nj++) {
                    mma_tf32_f4(acc[mi][nj], ua[mi], ub[mi], vb[nj].x, vb[nj].y);
                    float4 ta = make_float4(ua[mi].z, ua[mi].w, 0.f, 0.f);
                    float4 tb = make_float4(ub[mi].z, ub[mi].w, 0.f, 0.f);
                    mma_tf32_f4(acc[mi][nj], ta, tb, vb[nj].z, vb[nj].w);
                }
        }
    }

#pragma unroll
    for (int mi = 0; mi < 4; mi++) {
#pragma unroll
        for (int nj = 0; nj < 4; nj++) {
            int n = bn + wn * 32 + nj * 8 + t * 2;
            float b0 = bias[n], b1 = bias[n + 1];
#pragma unroll
            for (int rr = 0; rr < 2; rr++) {
                int m = bm + wm * 64 + mi * 16 + g + rr * 8;
                float v0 = __uint_as_float(f2tf32(acc[mi][nj][rr * 2] + b0));
                float v1 = __uint_as_float(f2tf32(acc[mi][nj][rr * 2 + 1] + b1));
                int s  = m & (N_seq - 1);
                int bb = m / N_seq;
                int h  = n >> 6;
                int hd = n & 63;
                int bh = bb * H_ + h;
                if (mode == 0) {
                    *reinterpret_cast<float2*>(
                        &Y[(((size_t)bh * NQ_ + s) << 6) + hd]) = make_float2(v0, v1);
                } else if (mode == 1) {
                    size_t base2 = (((size_t)bh * NK_ + s)) * 32;
                    int o  = ((hd >> 4) << 3) + (hd & 3) * 2 + ((hd >> 3) & 1);
                    int hf = (hd >> 2) & 1;
                    Y[(base2 + o) * 2 + hf]     = v0;
                    Y[(base2 + o + 2) * 2 + hf] = v1;
                } else {
                    int sl = s & 63;
                    int o  = ((sl >> 4) << 3) + (sl & 3) * 2 + ((sl >> 3) & 1);
                    int hf = (sl >> 2) & 1;
                    size_t base2 = (((size_t)bh * (NK_ / 64) + (s >> 6)) * 64 + hd) * 32;
                    Y[(base2 + o) * 2 + hf]      = v0;
                    Y[(base2 + 32 + o) * 2 + hf] = v1;
                }
            }
        }
    }
}

// ---------------------------------------------------------------------------
// Output projection, retiled 64x128 (grid (32,4) = 128 CTAs; warp tile 32x32).
// ---------------------------------------------------------------------------
#define POX 2304    // 64*36 floats per X stage
#define POW 4608    // 128*36 floats per W stage

__global__ __launch_bounds__(256, 2) void proj_out(
    const float* __restrict__ X, const float* __restrict__ W,
    const float* __restrict__ bias, float* __restrict__ Y)
{
    extern __shared__ float psm[];
    float* Xs = psm;                 // [2][POX]
    float* Ws = psm + 2 * POX;       // [2][POW]

    const int tid  = threadIdx.x;
    const int lane = tid & 31;
    const int w    = tid >> 5;
    const int wm   = w >> 2;         // 0..1 (32 rows)
    const int wn   = w & 3;          // 0..3 (32 cols)
    const int g    = lane >> 2;
    const int t    = lane & 3;
    const int bm   = blockIdx.x * 64;
    const int bn   = blockIdx.y * 128;

    unsigned xs_u = (unsigned)__cvta_generic_to_shared(Xs);
    unsigned ws_u = (unsigned)__cvta_generic_to_shared(Ws);

    float acc[2][4][4];
#pragma unroll
    for (int mi = 0; mi < 2; mi++)
#pragma unroll
        for (int nj = 0; nj < 4; nj++)
#pragma unroll
            for (int rr = 0; rr < 4; rr++) acc[mi][nj][rr] = 0.0f;

#pragma unroll
    for (int it = 0; it < 2; it++) {          // X: 512 chunks
        int i = it * 256 + tid;
        int r = i >> 3, c = (i & 7) * 4;
        cpa16(xs_u + (r * 36 + c) * 4, X + (size_t)(bm + r) * D_ + c);
    }
#pragma unroll
    for (int it = 0; it < 4; it++) {          // W: 1024 chunks
        int i = it * 256 + tid;
        int r = i >> 3, c = (i & 7) * 4;
        cpa16(ws_u + (r * 36 + c) * 4, W + (size_t)(bn + r) * D_ + c);
    }
    cpa_commit();

    for (int ki = 0; ki < 16; ki++) {
        cpa_wait<0>();
        __syncthreads();
        if (ki < 15) {
            int k0 = (ki + 1) * 32;
            int stx = ((ki + 1) & 1) * POX;
            int stw = ((ki + 1) & 1) * POW;
#pragma unroll
            for (int it = 0; it < 2; it++) {
                int i = it * 256 + tid;
                int r = i >> 3, c = (i & 7) * 4;
                cpa16(xs_u + (stx + r * 36 + c) * 4,
                      X + (size_t)(bm + r) * D_ + k0 + c);
            }
#pragma unroll
            for (int it = 0; it < 4; it++) {
                int i = it * 256 + tid;
                int r = i >> 3, c = (i & 7) * 4;
                cpa16(ws_u + (stw + r * 36 + c) * 4,
                      W + (size_t)(bn + r) * D_ + k0 + c);
            }
            cpa_commit();
        }
        const float* Xc = Xs + (ki & 1) * POX;
        const float* Wc = Ws + (ki & 1) * POW;

#pragma unroll
        for (int k8 = 0; k8 < 4; k8++) {
            unsigned a[2][4], b[4][2];
            int kk = k8 * 8 + t;
#pragma unroll
            for (int mi = 0; mi < 2; mi++) {
                int r = wm * 32 + mi * 16 + g;
                a[mi][0] = f2tf32(Xc[r * 36 + kk]);
                a[mi][1] = f2tf32(Xc[(r + 8) * 36 + kk]);
                a[mi][2] = f2tf32(Xc[r * 36 + kk + 4]);
                a[mi][3] = f2tf32(Xc[(r + 8) * 36 + kk + 4]);
            }
#pragma unroll
            for (int nj = 0; nj < 4; nj++) {
                int n = wn * 32 + nj * 8 + g;
                b[nj][0] = f2tf32(Wc[n * 36 + kk]);
                b[nj][1] = f2tf32(Wc[n * 36 + kk + 4]);
            }
#pragma unroll
            for (int mi = 0; mi < 2; mi++)
#pragma unroll
                for (int nj = 0; nj < 4; nj++)
                    mma_tf32(acc[mi][nj], a[mi], b[nj]);
        }
    }

#pragma unroll
    for (int mi = 0; mi < 2; mi++) {
#pragma unroll
        for (int nj = 0; nj < 4; nj++) {
            int n = bn + wn * 32 + nj * 8 + t * 2;
            float b0 = bias[n], b1 = bias[n + 1];
#pragma unroll
            for (int rr = 0; rr < 2; rr++) {
                int m = bm + wm * 32 + mi * 16 + g + rr * 8;
                *reinterpret_cast<float2*>(&Y[(size_t)m * D_ + n]) =
                    make_float2(acc[mi][nj][rr * 2] + b0,
                                acc[mi][nj][rr * 2 + 1] + b1);
            }
        }
    }
}

// ---------------------------------------------------------------------------
// Two-phase TF32 fused attention (R13 version: 64 q-rows/CTA, grid 256).
// ---------------------------------------------------------------------------
#define KBUFB 16384            // 64 rows * 32 f2 * 8B
#define VBUFB 16384
#define ATT_SMEM_BYTES (2 * KBUFB + 2 * VBUFB)   // 65536

__global__ __launch_bounds__(128, 3) void attn_tc(
    const float* __restrict__ gQ, const float* __restrict__ gK,
    const float* __restrict__ gV, float* __restrict__ A_out,
    float* __restrict__ gctx)
{
    extern __shared__ char smc[];
    char* Kb = smc;                  // [2][KBUFB]
    char* Vb = smc + 2 * KBUFB;      // [2][VBUFB]

    const int tid  = threadIdx.x;
    const int lane = tid & 31;
    const int w    = tid >> 5;
    const int g    = lane >> 2;
    const int t    = lane & 3;
    const int bh   = blockIdx.x >> 3;
    const int qt   = blockIdx.x & 7;
    const int rw   = w * 16;
    const int sw   = (g & 1) << 2;

    const float*  Qg  = gQ + ((size_t)bh * NQ_ + qt * 64 + rw) * HD_;
    const float2* Kg2 = (const float2*)gK + (size_t)bh * NK_ * 32;
    const float2* Vg2 = (const float2*)gV + (size_t)bh * NK_ * 32;
    float* Ab = A_out + ((size_t)bh * NQ_ + qt * 64) * NK_;

    unsigned kb_u = (unsigned)__cvta_generic_to_shared(Kb);
    unsigned vb_u = (unsigned)__cvta_generic_to_shared(Vb);

    unsigned qa[8][4];
#pragma unroll
    for (int k8 = 0; k8 < 8; k8++) {
        int kk = k8 * 8 + t;
        qa[k8][0] = __float_as_uint(Qg[(size_t)g * HD_ + kk]);
        qa[k8][1] = __float_as_uint(Qg[(size_t)(g + 8) * HD_ + kk]);
        qa[k8][2] = __float_as_uint(Qg[(size_t)g * HD_ + kk + 4]);
        qa[k8][3] = __float_as_uint(Qg[(size_t)(g + 8) * HD_ + kk + 4]);
    }

    const int cr = tid >> 4;
    const int cc = tid & 15;

    // ================= PHASE 1: row sums (K only) =================
#pragma unroll
    for (int it = 0; it < 8; it++) {
        int r = it * 8 + cr;
        cpa16(kb_u + (r * 16 + (cc ^ ((r & 1) << 2))) * 16,
              Kg2 + (size_t)r * 32 + cc * 2);
    }
    cpa_commit();

    float psum0 = 0.0f, psum1 = 0.0f;

    for (int kt = 0; kt < 64; kt++) {
        cpa_wait<0>();
        __syncthreads();
        if (kt < 63) {
            const float2* Kn = Kg2 + (size_t)(kt + 1) * 64 * 32;
            unsigned kdst = kb_u + ((kt + 1) & 1) * KBUFB;
#pragma unroll
            for (int it = 0; it < 8; it++) {
                int r = it * 8 + cr;
                cpa16(kdst + (r * 16 + (cc ^ ((r & 1) << 2))) * 16,
                      Kn + (size_t)r * 32 + cc * 2);
            }
            cpa_commit();
        }
        const char* Ksm = Kb + (kt & 1) * KBUFB;

        float s[8][4];
#pragma unroll
        for (int nj = 0; nj < 8; nj++)
#pragma unroll
            for (int rr = 0; rr < 4; rr++) s[nj][rr] = 0.0f;

#pragma unroll
        for (int p = 0; p < 4; p++) {
#pragma unroll
            for (int nj = 0; nj < 8; nj++) {
                int unit = (nj * 8 + g) * 16 + ((p * 4 + t) ^ sw);
                float4 u = *reinterpret_cast<const float4*>(Ksm + unit * 16);
                mma_tf32_u(s[nj], qa[2 * p],
                           __float_as_uint(u.x), __float_as_uint(u.y));
                mma_tf32_u(s[nj], qa[2 * p + 1],
                           __float_as_uint(u.z), __float_as_uint(u.w));
            }
        }

#pragma unroll
        for (int nj = 0; nj < 8; nj++) {
            psum0 += exp2f(s[nj][0] * EXPC) + exp2f(s[nj][1] * EXPC);
            psum1 += exp2f(s[nj][2] * EXPC) + exp2f(s[nj][3] * EXPC);
        }
    }

    psum0 += __shfl_xor_sync(0xffffffffu, psum0, 1);
    psum0 += __shfl_xor_sync(0xffffffffu, psum0, 2);
    psum1 += __shfl_xor_sync(0xffffffffu, psum1, 1);
    psum1 += __shfl_xor_sync(0xffffffffu, psum1, 2);
    const float li0 = 1.0f / psum0;
    const float li1 = 1.0f / psum1;

    // ================= PHASE 2: A + ctx =================
#pragma unroll
    for (int it = 0; it < 8; it++) {
        int r = it * 8 + cr;
        unsigned doff = (r * 16 + (cc ^ ((r & 1) << 2))) * 16;
        cpa16(kb_u + doff, Kg2 + (size_t)r * 32 + cc * 2);
        cpa16(vb_u + doff, Vg2 + (size_t)r * 32 + cc * 2);
    }
    cpa_commit();

    float ctx[8][4];
#pragma unroll
    for (int nj = 0; nj < 8; nj++)
#pragma unroll
        for (int rr = 0; rr < 4; rr++) ctx[nj][rr] = 0.0f;

    const int srcA = (lane & ~3) | (t >> 1);
    const int srcB = srcA + 2;
    const bool sel = (t & 1);

    for (int kt = 0; kt < 64; kt++) {
        cpa_wait<0>();
        __syncthreads();
        if (kt < 63) {
            const float2* Kn = Kg2 + (size_t)(kt + 1) * 64 * 32;
            const float2* Vn = Vg2 + (size_t)(kt + 1) * 64 * 32;
            unsigned kdst = kb_u + ((kt + 1) & 1) * KBUFB;
            unsigned vdst = vb_u + ((kt + 1) & 1) * VBUFB;
#pragma unroll
            for (int it = 0; it < 8; it++) {
                int r = it * 8 + cr;
                unsigned doff = (r * 16 + (cc ^ ((r & 1) << 2))) * 16;
                cpa16(kdst + doff, Kn + (size_t)r * 32 + cc * 2);
                cpa16(vdst + doff, Vn + (size_t)r * 32 + cc * 2);
            }
            cpa_commit();
        }
        const char* Ksm = Kb + (kt & 1) * KBUFB;
        const char* Vsm = Vb + (kt & 1) * VBUFB;

        float s[8][4];
#pragma unroll
        for (int nj = 0; nj < 8; nj++)
#pragma unroll
            for (int rr = 0; rr < 4; rr++) s[nj][rr] = 0.0f;

#pragma unroll
        for (int p = 0; p < 4; p++) {
#pragma unroll
            for (int nj = 0; nj < 8; nj++) {
                int unit = (nj * 8 + g) * 16 + ((p * 4 + t) ^ sw);
                float4 u = *reinterpret_cast<const float4*>(Ksm + unit * 16);
                mma_tf32_u(s[nj], qa[2 * p],
                           __float_as_uint(u.x), __float_as_uint(u.y));
                mma_tf32_u(s[nj], qa[2 * p + 1],
                           __float_as_uint(u.z), __float_as_uint(u.w));
            }
        }

        unsigned u0[8], u1[8], u2[8], u3[8];
#pragma unroll
        for (int nj = 0; nj < 8; nj++) {
            float p0 = exp2f(s[nj][0] * EXPC) * li0;
            float p1 = exp2f(s[nj][1] * EXPC) * li0;
            float p2 = exp2f(s[nj][2] * EXPC) * li1;
            float p3 = exp2f(s[nj][3] * EXPC) * li1;
            int col = kt * 64 + nj * 8 + t * 2;
            *reinterpret_cast<float2*>(
                &Ab[(size_t)(rw + g) * NK_ + col]) = make_float2(p0, p1);
            *reinterpret_cast<float2*>(
                &Ab[(size_t)(rw + g + 8) * NK_ + col]) = make_float2(p2, p3);
            u0[nj] = f2tf32(p0);
            u1[nj] = f2tf32(p1);
            u2[nj] = f2tf32(p2);
            u3[nj] = f2tf32(p3);
        }

#pragma unroll
        for (int p = 0; p < 4; p++) {
            unsigned paE[4], paO[4];
#pragma unroll
            for (int e = 0; e < 2; e++) {
                int c = 2 * p + e;
                unsigned x0 = __shfl_sync(0xffffffffu, u0[c], srcA);
                unsigned x1 = __shfl_sync(0xffffffffu, u1[c], srcA);
                unsigned y0 = __shfl_sync(0xffffffffu, u0[c], srcB);
                unsigned y1 = __shfl_sync(0xffffffffu, u1[c], srcB);
                unsigned z0 = __shfl_sync(0xffffffffu, u2[c], srcA);
                unsigned z1 = __shfl_sync(0xffffffffu, u3[c], srcA);
                unsigned w0 = __shfl_sync(0xffffffffu, u2[c], srcB);
                unsigned w1 = __shfl_sync(0xffffffffu, u3[c], srcB);
                unsigned* pa = e ? paO : paE;
                pa[0] = sel ? x1 : x0;
                pa[1] = sel ? z1 : z0;
                pa[2] = sel ? y1 : y0;
                pa[3] = sel ? w1 : w0;
            }
#pragma unroll
            for (int nj = 0; nj < 8; nj++) {
                int unit = (nj * 8 + g) * 16 + ((p * 4 + t) ^ sw);
                float4 u = *reinterpret_cast<const float4*>(Vsm + unit * 16);
                mma_tf32_u(ctx[nj], paE,
                           __float_as_uint(u.x), __float_as_uint(u.y));
                mma_tf32_u(ctx[nj], paO,
                           __float_as_uint(u.z), __float_as_uint(u.w));
            }
        }
    }

    const int b0 = bh >> 3;
    const int h  = bh & 7;
#pragma unroll
    for (int nj = 0; nj < 8; nj++) {
        int hd = nj * 8 + t * 2;
#pragma unroll
        for (int rr = 0; rr < 2; rr++) {
            int q = qt * 64 + rw + g + rr * 8;
            float2 v = make_float2(ctx[nj][rr * 2], ctx[nj][rr * 2 + 1]);
            *reinterpret_cast<float2*>(
                &gctx[((size_t)b0 * NQ_ + q) * D_ + h * 64 + hd]) = v;
        }
    }
}

// ---------------------------------------------------------------------------
extern "C" void kernel_launch(void* const* d_in, const int* in_sizes, int n_in,
                              void* d_out, int out_size)
{
    const float* q  = (const float*)d_in[0];
    const float* k  = (const float*)d_in[1];
    const float* v  = (const float*)d_in[2];
    const float* Wq = (const float*)d_in[3];
    const float* bq = (const float*)d_in[4];
    const float* Wk = (const float*)d_in[5];
    const float* bk = (const float*)d_in[6];
    const float* Wv = (const float*)d_in[7];
    const float* bv = (const float*)d_in[8];
    const float* Wo = (const float*)d_in[9];
    const float* bo = (const float*)d_in[10];

    float* out = (float*)d_out;                         // [B, NQ, D]
    float* A   = out + (size_t)B_ * NQ_ * D_;           // [B, H, NQ, NK]

    float *gQ, *gK, *gV, *gctx, *gXq, *gXk, *gXv, *gWq, *gWk, *gWv;
    cudaGetSymbolAddress((void**)&gQ,  g_Q);
    cudaGetSymbolAddress((void**)&gK,  g_K);
    cudaGetSymbolAddress((void**)&gV,  g_V);
    cudaGetSymbolAddress((void**)&gctx, g_ctx);
    cudaGetSymbolAddress((void**)&gXq, g_Xq);
    cudaGetSymbolAddress((void**)&gXk, g_Xk);
    cudaGetSymbolAddress((void**)&gXv, g_Xv);
    cudaGetSymbolAddress((void**)&gWq, g_Wq);
    cudaGetSymbolAddress((void**)&gWk, g_Wk);
    cudaGetSymbolAddress((void**)&gWv, g_Wv);

    const int pk_smem = 4 * PKSTG * 4;                 // 65536 B
    const int po_smem = (2 * POX + 2 * POW) * 4;       // 55296 B
    cudaFuncSetAttribute(proj_qkv,
        cudaFuncAttributeMaxDynamicSharedMemorySize, pk_smem);
    cudaFuncSetAttribute(proj_out,
        cudaFuncAttributeMaxDynamicSharedMemorySize, po_smem);
    cudaFuncSetAttribute(attn_tc,
        cudaFuncAttributeMaxDynamicSharedMemorySize, ATT_SMEM_BYTES);

    prepack<<<18176, 256>>>(q, k, v, Wq, Wk, Wv,
                            gXq, gXk, gXv, gWq, gWk, gWv);
    proj_qkv<<<dim3(272, 4), 256, pk_smem>>>(
        gXq, gWq, bq, gXk, gWk, bk, gXv, gWv, bv, gQ, gK, gV);
    attn_tc<<<256, 128, ATT_SMEM_BYTES>>>(gQ, gK, gV, A, gctx);
    proj_out<<<dim3(32, 4), 256, po_smem>>>(gctx, Wo, bo, out);
}